// round 14
// baseline (speedup 1.0000x reference)
#include <cuda_runtime.h>
#include <math.h>
#include <float.h>
#include <stdint.h>

// Problem constants (fixed by the dataset)
#define B_   256
#define N_   512
#define K_   4
#define D_   9
#define L_   32
#define NCLS 9
#define BETA 0.01f
#define CW   0.001f

#define PTHREADS 64             // partial kernel threads (4 queries each)
#define QPT      4              // queries per thread
#define NPART    (B_ * 4)       // 4 partial CTAs per batch

__device__ float    g_partial[NPART];
__device__ unsigned g_count[B_];   // zero-init; each use resets itself -> graph-replay safe

// ---- f32x2 packed helpers (Blackwell) ----
__device__ __forceinline__ uint64_t pack2(float lo, float hi) {
    uint64_t r; asm("mov.b64 %0, {%1, %2};" : "=l"(r) : "f"(lo), "f"(hi)); return r;
}
__device__ __forceinline__ void unpack2(uint64_t v, float& lo, float& hi) {
    asm("mov.b64 {%0, %1}, %2;" : "=f"(lo), "=f"(hi) : "l"(v));
}
__device__ __forceinline__ uint64_t fma2(uint64_t a, uint64_t b, uint64_t c) {
    uint64_t d; asm("fma.rn.f32x2 %0, %1, %2, %3;" : "=l"(d) : "l"(a), "l"(b), "l"(c)); return d;
}
__device__ __forceinline__ uint64_t mul2(uint64_t a, uint64_t b) {
    uint64_t d; asm("mul.rn.f32x2 %0, %1, %2;" : "=l"(d) : "l"(a), "l"(b)); return d;
}
__device__ __forceinline__ uint64_t add2(uint64_t a, uint64_t b) {
    uint64_t d; asm("add.rn.f32x2 %0, %1, %2;" : "=l"(d) : "l"(a), "l"(b)); return d;
}

// Bit-identical recompute of one parity lane within the winning 8-iter block;
// returns absolute neighbor index of the FIRST element equal to target.
// (f32x2 per-lane rounding == scalar FFMA: validated empirically R8->R12.)
__device__ __forceinline__ int rescan_first(const float* __restrict__ fxy,
                                            const float* __restrict__ fzw,
                                            const float* __restrict__ fnn,
                                            int blk, int parity,
                                            float4 x, float x2, float target)
{
    #pragma unroll 1
    for (int j = 0; j < 8; ++j) {
        int k = blk * 8 + j;
        float yx = fxy[k * 4 + parity];
        float yy = fxy[k * 4 + 2 + parity];
        float yz = fzw[k * 4 + parity];
        float yw = fzw[k * 4 + 2 + parity];
        float nn = fnn[k * 2 + parity];
        // same chain as packed loop: t = w*yw; t = z*yz+t; t = y*yy+t; t = x*yx+t
        float xy = fmaf(x.x, yx, fmaf(x.y, yy, fmaf(x.z, yz, x.w * yw)));
        float d  = fmaf(-2.f, xy, x2 + nn);
        if (d == target) return 2 * k + parity;
    }
    return blk * 16 + parity;   // unreachable (target always present in its block)
}

// Each CTA: one Chamfer direction (dir) for one half of the queries (half)
// of one batch (b). blockIdx.x = b*4 + dir*2 + half.
__global__ __launch_bounds__(PTHREADS, 8)
void chamfer_partial(const float* __restrict__ kine_in,
                     const float* __restrict__ class_in,
                     const float* __restrict__ kine_pr,
                     const float* __restrict__ class_pr,
                     const float* __restrict__ mu,
                     const float* __restrict__ log_var,
                     float* __restrict__ out)
{
    // Neighbor tile, pair-interleaved for f32x2 (see loader for float layout)
    __shared__ ulonglong2 s_xy[N_ / 2];
    __shared__ ulonglong2 s_zw[N_ / 2];
    __shared__ uint64_t   s_nn[N_ / 2];
    __shared__ float      s_red1[2];
    __shared__ float      s_red2[2];
    __shared__ float      s_cnt_in[NCLS];
    __shared__ float      s_cnt_pr[NCLS];

    const int bid  = blockIdx.x;
    const int b    = bid >> 2;
    const int q    = bid & 3;
    const int dir  = q >> 1;     // 0: input->pred, 1: pred->input
    const int half = q & 1;
    const int t    = threadIdx.x;

    const float* kq = (dir == 0) ? kine_in : kine_pr;
    const float* kn = (dir == 0) ? kine_pr : kine_in;
    const float4* kq4 = (const float4*)(kq + (size_t)b * N_ * K_);
    const float4* kn4 = (const float4*)(kn + (size_t)b * N_ * K_);

    float* fxy = (float*)s_xy;
    float* fzw = (float*)s_zw;
    float* fnn = (float*)s_nn;

    // ---- load neighbor tile into pair-interleaved smem, precompute norms ----
    #pragma unroll
    for (int r = 0; r < 8; ++r) {
        int p = t + r * PTHREADS;
        float4 v = kn4[p];
        int k = p >> 1, lane = p & 1;
        fxy[k * 4 + lane]     = v.x;
        fxy[k * 4 + 2 + lane] = v.y;
        fzw[k * 4 + lane]     = v.z;
        fzw[k * 4 + 2 + lane] = v.w;
        fnn[k * 2 + lane] = fmaf(v.x, v.x, fmaf(v.y, v.y, fmaf(v.z, v.z, v.w * v.w)));
    }
    if (t < NCLS) { s_cnt_in[t] = 0.f; s_cnt_pr[t] = 0.f; }

    // ---- this thread's 4 query points (registers), broadcast-packed ----
    float4 xq[QPT]; float xq2[QPT];
    uint64_t qx[QPT], qy[QPT], qz[QPT], qw[QPT], qn[QPT];
    #pragma unroll
    for (int r = 0; r < QPT; ++r) {
        float4 v = kq4[half * 256 + t + r * PTHREADS];
        xq[r]  = v;
        xq2[r] = fmaf(v.x, v.x, fmaf(v.y, v.y, fmaf(v.z, v.z, v.w * v.w)));
        qx[r] = pack2(v.x, v.x);
        qy[r] = pack2(v.y, v.y);
        qz[r] = pack2(v.z, v.z);
        qw[r] = pack2(v.w, v.w);
        qn[r] = pack2(xq2[r], xq2[r]);
    }
    const uint64_t neg2 = pack2(-2.f, -2.f);
    __syncthreads();

    // ---- blocked min over all 512 neighbors; 8 streams (4 queries x 2 parities) ----
    float gmin[2 * QPT]; int gblk[2 * QPT];
    #pragma unroll
    for (int s = 0; s < 2 * QPT; ++s) { gmin[s] = FLT_MAX; gblk[s] = 0; }

    #pragma unroll 1
    for (int blk = 0; blk < (N_ / 2) / 8; ++blk) {
        float bmin[2 * QPT];
        #pragma unroll
        for (int s = 0; s < 2 * QPT; ++s) bmin[s] = FLT_MAX;

        #pragma unroll
        for (int j = 0; j < 8; ++j) {
            int k = blk * 8 + j;
            ulonglong2 pxy = s_xy[k];
            ulonglong2 pzw = s_zw[k];
            uint64_t   pnn = s_nn[k];
            #pragma unroll
            for (int r = 0; r < QPT; ++r) {
                uint64_t tt = mul2(qw[r], pzw.y);
                tt = fma2(qz[r], pzw.x, tt);
                tt = fma2(qy[r], pxy.y, tt);
                tt = fma2(qx[r], pxy.x, tt);
                uint64_t dd = fma2(neg2, tt, add2(qn[r], pnn));
                float de, dodd; unpack2(dd, de, dodd);
                bmin[2 * r]     = fminf(bmin[2 * r],     de);
                bmin[2 * r + 1] = fminf(bmin[2 * r + 1], dodd);
            }
        }
        // strict < : earliest block holding the global min wins
        #pragma unroll
        for (int s = 0; s < 2 * QPT; ++s)
            if (bmin[s] < gmin[s]) { gmin[s] = bmin[s]; gblk[s] = blk; }
    }

    // ---- recover first-occurrence indices + class dots, per query ----
    const float* cinB = class_in + (size_t)b * N_ * D_;
    const float* cprB = class_pr + (size_t)b * N_ * D_;
    const float* qcls = (dir == 0) ? cinB : cprB;
    const float* ncls = (dir == 0) ? cprB : cinB;

    float chamfer = 0.f, dots = 0.f;
    #pragma unroll 1
    for (int r = 0; r < QPT; ++r) {
        float ge = gmin[2 * r], go = gmin[2 * r + 1];
        int   be = gblk[2 * r], bo = gblk[2 * r + 1];
        float best; int idx;
        if (ge < go) {
            best = ge; idx = rescan_first(fxy, fzw, fnn, be, 0, xq[r], xq2[r], ge);
        } else if (go < ge) {
            best = go; idx = rescan_first(fxy, fzw, fnn, bo, 1, xq[r], xq2[r], go);
        } else {
            best = ge;
            int ie = rescan_first(fxy, fzw, fnn, be, 0, xq[r], xq2[r], ge);
            int io = rescan_first(fxy, fzw, fnn, bo, 1, xq[r], xq2[r], go);
            idx = min(ie, io);
        }
        chamfer += fmaxf(best, 0.f);

        const int p = half * 256 + t + r * PTHREADS;
        const float* g1 = ncls + (size_t)idx * D_;
        const float* q1 = qcls + (size_t)p * D_;
        float d1 = 0.f;
        #pragma unroll
        for (int d = 0; d < D_; ++d) d1 = fmaf(g1[d], q1[d], d1);
        dots += d1;
    }

    // ---- q==0 CTA also builds both histograms (512 pts x 2, 8 pts/thread) ----
    if (q == 0) {
        #pragma unroll 1
        for (int r = 0; r < 8; ++r) {
            int p = t + r * PTHREADS;
            {
                const float* c = cinB + (size_t)p * D_;
                int li = 0; float mv = c[0];
                #pragma unroll
                for (int d = 1; d < D_; ++d) if (c[d] > mv) { mv = c[d]; li = d; }
                atomicAdd(&s_cnt_in[li], 1.f);
            }
            {
                const float* c = cprB + (size_t)p * D_;   // exp monotonic -> raw-logit argmax
                int lp = 0; float mv = c[0];
                #pragma unroll
                for (int d = 1; d < D_; ++d) if (c[d] > mv) { mv = c[d]; lp = d; }
                atomicAdd(&s_cnt_pr[lp], 1.f);
            }
        }
    }

    // ---- block reduction over 2 warps ----
    float v1 = chamfer;
    float v2 = dots;
    #pragma unroll
    for (int o = 16; o > 0; o >>= 1) {
        v1 += __shfl_down_sync(0xFFFFFFFFu, v1, o);
        v2 += __shfl_down_sync(0xFFFFFFFFu, v2, o);
    }
    const int warp = t >> 5, lane = t & 31;
    if (lane == 0) { s_red1[warp] = v1; s_red2[warp] = v2; }
    __syncthreads();   // also orders histogram atomics

    if (t < 32) {
        float a1 = (t < 2) ? s_red1[t] : 0.f;
        float a2s = (t < 2) ? s_red2[t] : 0.f;
        float kv = 0.f;
        if (q == 0) {
            float m_  = mu[(size_t)b * L_ + t];
            float lv_ = log_var[(size_t)b * L_ + t];
            kv = 1.f + lv_ - m_ * m_ - expf(lv_);
        }
        #pragma unroll
        for (int o = 16; o > 0; o >>= 1) {
            a1  += __shfl_down_sync(0xFFFFFFFFu, a1, o);
            a2s += __shfl_down_sync(0xFFFFFFFFu, a2s, o);
            kv  += __shfl_down_sync(0xFFFFFFFFu, kv, o);
        }
        if (t == 0) {
            float part = (1.f - BETA) * (a1 - a2s);
            if (q == 0) {
                float kl = -0.5f * kv;
                float cnum = 0.f;
                cnum += 2.f   * fabsf(s_cnt_pr[0] - s_cnt_in[0]);
                #pragma unroll
                for (int c = 1; c < NCLS - 1; ++c) cnum += fabsf(s_cnt_pr[c] - s_cnt_in[c]);
                cnum += 100.f * fabsf(s_cnt_pr[NCLS - 1] - s_cnt_in[NCLS - 1]);
                part += (1.f - BETA) * CW * cnum + BETA * kl;
            }
            g_partial[bid] = part;

            // ---- last-arrival CTA of this batch finalizes (fixed-order sum => deterministic) ----
            __threadfence();
            unsigned prev = atomicAdd(&g_count[b], 1u);
            if (prev == 3u) {
                __threadfence();
                float s = ((__ldcg(&g_partial[4 * b + 0]) + __ldcg(&g_partial[4 * b + 1]))
                           + __ldcg(&g_partial[4 * b + 2])) + __ldcg(&g_partial[4 * b + 3]);
                out[b] = s;
                g_count[b] = 0u;   // reset for next graph replay
            }
        }
    }
}

extern "C" void kernel_launch(void* const* d_in, const int* in_sizes, int n_in,
                              void* d_out, int out_size)
{
    const float* kine_in  = (const float*)d_in[0];
    const float* class_in = (const float*)d_in[1];
    const float* kine_pr  = (const float*)d_in[2];
    const float* class_pr = (const float*)d_in[3];
    const float* mu       = (const float*)d_in[4];
    const float* log_var  = (const float*)d_in[5];
    float* out = (float*)d_out;

    chamfer_partial<<<NPART, PTHREADS>>>(kine_in, class_in, kine_pr, class_pr, mu, log_var, out);
}

// round 16
// speedup vs baseline: 1.1468x; 1.1468x over previous
#include <cuda_runtime.h>
#include <math.h>
#include <float.h>
#include <stdint.h>

// Problem constants (fixed by the dataset)
#define B_   256
#define N_   512
#define K_   4
#define D_   9
#define L_   32
#define NCLS 9
#define BETA 0.01f
#define CW   0.001f

#define PTHREADS 128            // partial kernel threads (2 queries each)
#define NPART    (B_ * 4)       // 4 partial CTAs per batch

__device__ float    g_partial[NPART];
__device__ unsigned g_count[B_];   // zero-init; each use resets itself -> graph-replay safe

// ---- f32x2 packed helpers (Blackwell) ----
__device__ __forceinline__ uint64_t pack2(float lo, float hi) {
    uint64_t r; asm("mov.b64 %0, {%1, %2};" : "=l"(r) : "f"(lo), "f"(hi)); return r;
}
__device__ __forceinline__ void unpack2(uint64_t v, float& lo, float& hi) {
    asm("mov.b64 {%0, %1}, %2;" : "=f"(lo), "=f"(hi) : "l"(v));
}
__device__ __forceinline__ uint64_t fma2(uint64_t a, uint64_t b, uint64_t c) {
    uint64_t d; asm("fma.rn.f32x2 %0, %1, %2, %3;" : "=l"(d) : "l"(a), "l"(b), "l"(c)); return d;
}
__device__ __forceinline__ uint64_t mul2(uint64_t a, uint64_t b) {
    uint64_t d; asm("mul.rn.f32x2 %0, %1, %2;" : "=l"(d) : "l"(a), "l"(b)); return d;
}
__device__ __forceinline__ uint64_t add2(uint64_t a, uint64_t b) {
    uint64_t d; asm("add.rn.f32x2 %0, %1, %2;" : "=l"(d) : "l"(a), "l"(b)); return d;
}

// Bit-identical recompute of one parity lane within the winning 8-iter block;
// returns absolute neighbor index of the FIRST element equal to target.
// Norm recomputed with the SAME chain used in the packed loop (bit-identical;
// packed==scalar per-lane validated R8->R12).
__device__ __forceinline__ int rescan_first(const float* __restrict__ fxy,
                                            const float* __restrict__ fzw,
                                            int blk, int parity,
                                            float4 x, float x2, float target)
{
    #pragma unroll 1
    for (int j = 0; j < 8; ++j) {
        int k = blk * 8 + j;
        float yx = fxy[k * 4 + parity];
        float yy = fxy[k * 4 + 2 + parity];
        float yz = fzw[k * 4 + parity];
        float yw = fzw[k * 4 + 2 + parity];
        // norm chain identical to packed loop
        float nn = fmaf(yx, yx, fmaf(yy, yy, fmaf(yz, yz, yw * yw)));
        float xy = fmaf(x.x, yx, fmaf(x.y, yy, fmaf(x.z, yz, x.w * yw)));
        float d  = fmaf(-2.f, xy, x2 + nn);
        if (d == target) return 2 * k + parity;
    }
    return blk * 16 + parity;   // unreachable (target always present in its block)
}

// Each CTA: one Chamfer direction (dir) for one half of the queries (half)
// of one batch (b). blockIdx.x = b*4 + dir*2 + half.
__global__ __launch_bounds__(PTHREADS, 6)
void chamfer_partial(const float* __restrict__ kine_in,
                     const float* __restrict__ class_in,
                     const float* __restrict__ kine_pr,
                     const float* __restrict__ class_pr,
                     const float* __restrict__ mu,
                     const float* __restrict__ log_var,
                     float* __restrict__ out)
{
    // Neighbor tile, pair-interleaved for f32x2:
    //   s_xy[k] = (x_{2k}, x_{2k+1}, y_{2k}, y_{2k+1})
    //   s_zw[k] = (z_{2k}, z_{2k+1}, w_{2k}, w_{2k+1})
    // Norms are RECOMPUTED in-loop (saves 1 LDS/pair on the binding L1 pipe).
    __shared__ ulonglong2 s_xy[N_ / 2];
    __shared__ ulonglong2 s_zw[N_ / 2];
    __shared__ float      s_red1[4];
    __shared__ float      s_red2[4];
    __shared__ float      s_cnt_in[NCLS];
    __shared__ float      s_cnt_pr[NCLS];

    const int bid  = blockIdx.x;
    const int b    = bid >> 2;
    const int q    = bid & 3;
    const int dir  = q >> 1;     // 0: input->pred, 1: pred->input
    const int half = q & 1;
    const int t    = threadIdx.x;

    const float* kq = (dir == 0) ? kine_in : kine_pr;
    const float* kn = (dir == 0) ? kine_pr : kine_in;
    const float4* kq4 = (const float4*)(kq + (size_t)b * N_ * K_);
    const float4* kn4 = (const float4*)(kn + (size_t)b * N_ * K_);

    float* fxy = (float*)s_xy;
    float* fzw = (float*)s_zw;

    // ---- load neighbor tile into pair-interleaved smem ----
    #pragma unroll
    for (int r = 0; r < 4; ++r) {
        int p = t + r * PTHREADS;
        float4 v = kn4[p];
        int k = p >> 1, lane = p & 1;
        fxy[k * 4 + lane]     = v.x;
        fxy[k * 4 + 2 + lane] = v.y;
        fzw[k * 4 + lane]     = v.z;
        fzw[k * 4 + 2 + lane] = v.w;
    }
    if (t < NCLS) { s_cnt_in[t] = 0.f; s_cnt_pr[t] = 0.f; }

    // ---- this thread's 2 query points (registers), broadcast-packed ----
    const int p0 = half * 256 + t;
    const int p1 = p0 + PTHREADS;
    const float4 xa = kq4[p0];
    const float4 xb = kq4[p1];
    const float xa2 = fmaf(xa.x, xa.x, fmaf(xa.y, xa.y, fmaf(xa.z, xa.z, xa.w * xa.w)));
    const float xb2 = fmaf(xb.x, xb.x, fmaf(xb.y, xb.y, fmaf(xb.z, xb.z, xb.w * xb.w)));

    const uint64_t ax = pack2(xa.x, xa.x), ay = pack2(xa.y, xa.y);
    const uint64_t az = pack2(xa.z, xa.z), aw = pack2(xa.w, xa.w);
    const uint64_t bx = pack2(xb.x, xb.x), by = pack2(xb.y, xb.y);
    const uint64_t bz = pack2(xb.z, xb.z), bw = pack2(xb.w, xb.w);
    const uint64_t a2 = pack2(xa2, xa2),   b2 = pack2(xb2, xb2);
    const uint64_t neg2 = pack2(-2.f, -2.f);
    __syncthreads();

    // ---- blocked min: values only via fminf; index deferred to block-id + rescan ----
    float gbae = FLT_MAX, gbao = FLT_MAX, gbbe = FLT_MAX, gbbo = FLT_MAX;
    int   blka_e = 0, blka_o = 0, blkb_e = 0, blkb_o = 0;

    #pragma unroll 1
    for (int blk = 0; blk < (N_ / 2) / 8; ++blk) {
        float bae = FLT_MAX, bao = FLT_MAX, bbe = FLT_MAX, bbo = FLT_MAX;
        #pragma unroll
        for (int j = 0; j < 8; ++j) {
            int k = blk * 8 + j;
            ulonglong2 pxy = s_xy[k];     // .x = x-pair, .y = y-pair
            ulonglong2 pzw = s_zw[k];     // .x = z-pair, .y = w-pair

            // norm-pair recomputed (same chain as the old precompute: bit-identical)
            uint64_t pnn = mul2(pzw.y, pzw.y);
            pnn = fma2(pzw.x, pzw.x, pnn);
            pnn = fma2(pxy.y, pxy.y, pnn);
            pnn = fma2(pxy.x, pxy.x, pnn);

            uint64_t ta = mul2(aw, pzw.y);
            ta = fma2(az, pzw.x, ta);
            ta = fma2(ay, pxy.y, ta);
            ta = fma2(ax, pxy.x, ta);
            uint64_t da = fma2(neg2, ta, add2(a2, pnn));
            float dae, dao; unpack2(da, dae, dao);
            bae = fminf(bae, dae);
            bao = fminf(bao, dao);

            uint64_t tb = mul2(bw, pzw.y);
            tb = fma2(bz, pzw.x, tb);
            tb = fma2(by, pxy.y, tb);
            tb = fma2(bx, pxy.x, tb);
            uint64_t db = fma2(neg2, tb, add2(b2, pnn));
            float dbe, dbo; unpack2(db, dbe, dbo);
            bbe = fminf(bbe, dbe);
            bbo = fminf(bbo, dbo);
        }
        // strict < : earliest block holding the global min wins
        if (bae < gbae) { gbae = bae; blka_e = blk; }
        if (bao < gbao) { gbao = bao; blka_o = blk; }
        if (bbe < gbbe) { gbbe = bbe; blkb_e = blk; }
        if (bbo < gbbo) { gbbo = bbo; blkb_o = blk; }
    }

    // ---- recover first-occurrence indices (rescan winning blocks only) ----
    float besta, bestb; int idxa, idxb;
    if (gbae < gbao) {
        besta = gbae; idxa = rescan_first(fxy, fzw, blka_e, 0, xa, xa2, gbae);
    } else if (gbao < gbae) {
        besta = gbao; idxa = rescan_first(fxy, fzw, blka_o, 1, xa, xa2, gbao);
    } else {
        besta = gbae;
        int ie = rescan_first(fxy, fzw, blka_e, 0, xa, xa2, gbae);
        int io = rescan_first(fxy, fzw, blka_o, 1, xa, xa2, gbao);
        idxa = min(ie, io);
    }
    if (gbbe < gbbo) {
        bestb = gbbe; idxb = rescan_first(fxy, fzw, blkb_e, 0, xb, xb2, gbbe);
    } else if (gbbo < gbbe) {
        bestb = gbbo; idxb = rescan_first(fxy, fzw, blkb_o, 1, xb, xb2, gbbo);
    } else {
        bestb = gbbe;
        int ie = rescan_first(fxy, fzw, blkb_e, 0, xb, xb2, gbbe);
        int io = rescan_first(fxy, fzw, blkb_o, 1, xb, xb2, gbbo);
        idxb = min(ie, io);
    }
    besta = fmaxf(besta, 0.f);
    bestb = fmaxf(bestb, 0.f);

    // ---- class dots for this direction ----
    const float* cinB = class_in + (size_t)b * N_ * D_;
    const float* cprB = class_pr + (size_t)b * N_ * D_;
    const float* qcls = (dir == 0) ? cinB : cprB;
    const float* ncls = (dir == 0) ? cprB : cinB;

    float dots = 0.f;
    {
        const float* ga = ncls + (size_t)idxa * D_;
        const float* qa = qcls + (size_t)p0 * D_;
        const float* gb = ncls + (size_t)idxb * D_;
        const float* qb = qcls + (size_t)p1 * D_;
        float d1 = 0.f, d2 = 0.f;
        #pragma unroll
        for (int d = 0; d < D_; ++d) d1 = fmaf(ga[d], qa[d], d1);
        #pragma unroll
        for (int d = 0; d < D_; ++d) d2 = fmaf(gb[d], qb[d], d2);
        dots = d1 + d2;
    }

    // ---- q==0 CTA also builds both histograms ----
    if (q == 0) {
        #pragma unroll
        for (int r = 0; r < 4; ++r) {
            int p = t + r * PTHREADS;
            {
                const float* c = cinB + (size_t)p * D_;
                int li = 0; float mv = c[0];
                #pragma unroll
                for (int d = 1; d < D_; ++d) if (c[d] > mv) { mv = c[d]; li = d; }
                atomicAdd(&s_cnt_in[li], 1.f);
            }
            {
                const float* c = cprB + (size_t)p * D_;   // exp monotonic -> raw-logit argmax
                int lp = 0; float mv = c[0];
                #pragma unroll
                for (int d = 1; d < D_; ++d) if (c[d] > mv) { mv = c[d]; lp = d; }
                atomicAdd(&s_cnt_pr[lp], 1.f);
            }
        }
    }

    // ---- block reduction over 4 warps ----
    float v1 = besta + bestb;
    float v2 = dots;
    #pragma unroll
    for (int o = 16; o > 0; o >>= 1) {
        v1 += __shfl_down_sync(0xFFFFFFFFu, v1, o);
        v2 += __shfl_down_sync(0xFFFFFFFFu, v2, o);
    }
    const int warp = t >> 5, lane = t & 31;
    if (lane == 0) { s_red1[warp] = v1; s_red2[warp] = v2; }
    __syncthreads();

    if (t < 32) {
        float a1 = (t < 4) ? s_red1[t] : 0.f;
        float a2s = (t < 4) ? s_red2[t] : 0.f;
        float kv = 0.f;
        if (q == 0) {
            float m_  = mu[(size_t)b * L_ + t];
            float lv_ = log_var[(size_t)b * L_ + t];
            kv = 1.f + lv_ - m_ * m_ - expf(lv_);
        }
        #pragma unroll
        for (int o = 16; o > 0; o >>= 1) {
            a1  += __shfl_down_sync(0xFFFFFFFFu, a1, o);
            a2s += __shfl_down_sync(0xFFFFFFFFu, a2s, o);
            kv  += __shfl_down_sync(0xFFFFFFFFu, kv, o);
        }
        if (t == 0) {
            float part = (1.f - BETA) * (a1 - a2s);
            if (q == 0) {
                float kl = -0.5f * kv;
                float cnum = 0.f;
                cnum += 2.f   * fabsf(s_cnt_pr[0] - s_cnt_in[0]);
                #pragma unroll
                for (int c = 1; c < NCLS - 1; ++c) cnum += fabsf(s_cnt_pr[c] - s_cnt_in[c]);
                cnum += 100.f * fabsf(s_cnt_pr[NCLS - 1] - s_cnt_in[NCLS - 1]);
                part += (1.f - BETA) * CW * cnum + BETA * kl;
            }
            g_partial[bid] = part;

            // ---- last-arrival CTA of this batch finalizes (fixed-order sum => deterministic) ----
            __threadfence();
            unsigned prev = atomicAdd(&g_count[b], 1u);
            if (prev == 3u) {
                __threadfence();
                float s = ((__ldcg(&g_partial[4 * b + 0]) + __ldcg(&g_partial[4 * b + 1]))
                           + __ldcg(&g_partial[4 * b + 2])) + __ldcg(&g_partial[4 * b + 3]);
                out[b] = s;
                g_count[b] = 0u;   // reset for next graph replay
            }
        }
    }
}

extern "C" void kernel_launch(void* const* d_in, const int* in_sizes, int n_in,
                              void* d_out, int out_size)
{
    const float* kine_in  = (const float*)d_in[0];
    const float* class_in = (const float*)d_in[1];
    const float* kine_pr  = (const float*)d_in[2];
    const float* class_pr = (const float*)d_in[3];
    const float* mu       = (const float*)d_in[4];
    const float* log_var  = (const float*)d_in[5];
    float* out = (float*)d_out;

    chamfer_partial<<<NPART, PTHREADS>>>(kine_in, class_in, kine_pr, class_pr, mu, log_var, out);
}